// round 14
// baseline (speedup 1.0000x reference)
#include <cuda_runtime.h>
#include <math.h>

#define BB 256   // batch
#define NS 32    // spans
#define DD 512   // feature dim

#define KT 32    // k-chunk per gemm block (16 k-splits)
#define NSPLIT 16

// Scratch (allocation-free rule: __device__ globals)
__device__ float g_A[BB * DD];              // ner span-sums [b][d], pre-scaled 1/1024
__device__ float g_F[BB * DD];              // face span-sums [c][d]
__device__ float g_part[NSPLIT * BB * BB];  // per-k-split logits partials (4 MB)
__device__ float g_diag[BB];                // logp[b][b]
__device__ unsigned int g_cnt;              // lse arrival counter

// ---------------------------------------------------------------------------
// Kernel 1: span reductions. 512 blocks x 512 threads, one row per block.
// Balanced MLP: 2 batches of 4 independent LDG.128 (R12 high-occ/low-MLP and
// R13 low-occ/high-MLP bracketed the same ~9 us plateau; this sits between
// at ~36 regs / ~65% occ).
// ---------------------------------------------------------------------------
__global__ void reduce_spans(
        const float* __restrict__ face, const float* __restrict__ ner) {
    const int blk = blockIdx.x;
    const int tid = threadIdx.x;
    const int t4  = tid & 127;     // float4 index within row (128 * 4 = 512 d)
    const int grp = tid >> 7;      // span group 0..3 (8 spans each)

    if (blk == 0 && tid == 0) g_cnt = 0u;

    const bool is_ner = (blk < BB);
    const int row = is_ner ? blk : blk - BB;
    const float4* src = reinterpret_cast<const float4*>(
        (is_ner ? ner : face) + (size_t)row * NS * DD) + grp * 8 * (DD / 4) + t4;

    float4 s = make_float4(0.f, 0.f, 0.f, 0.f);
#pragma unroll
    for (int j = 0; j < 2; j++) {
        // 4 independent loads, tree-summed, then folded into s
        const float4 v0 = src[(j * 4 + 0) * (DD / 4)];
        const float4 v1 = src[(j * 4 + 1) * (DD / 4)];
        const float4 v2 = src[(j * 4 + 2) * (DD / 4)];
        const float4 v3 = src[(j * 4 + 3) * (DD / 4)];
        const float4 a01 = make_float4(v0.x + v1.x, v0.y + v1.y,
                                       v0.z + v1.z, v0.w + v1.w);
        const float4 a23 = make_float4(v2.x + v3.x, v2.y + v3.y,
                                       v2.z + v3.z, v2.w + v3.w);
        s.x += a01.x + a23.x;
        s.y += a01.y + a23.y;
        s.z += a01.z + a23.z;
        s.w += a01.w + a23.w;
    }

    __shared__ float4 sp[3][128];
    if (grp > 0) sp[grp - 1][t4] = s;
    __syncthreads();

    if (grp == 0) {
#pragma unroll
        for (int i = 0; i < 3; i++) {
            float4 v = sp[i][t4];
            s.x += v.x; s.y += v.y; s.z += v.z; s.w += v.w;
        }
        if (is_ner) {
            const float inv = 1.0f / 1024.0f;   // fold the 1/(N1*N2) mean
            s.x *= inv; s.y *= inv; s.z *= inv; s.w *= inv;
            reinterpret_cast<float4*>(g_A + row * DD)[t4] = s;
        } else {
            reinterpret_cast<float4*>(g_F + row * DD)[t4] = s;
        }
    }
}

// ---------------------------------------------------------------------------
// Kernel 2: smem-staged register-blocked SGEMM partial.
// Block = 64x64 C-tile, k-chunk of 32. Grid = 16 tiles x 16 k-splits = 256
// blocks x 256 threads. Mainloop per k: 2 x LDS.128 + 16 FMA (4x4 reg tile).
// Output: 4 plain STG.128 per thread into this k-split's private slice,
// layout g_part[ks][row][col] so kernel 3's reads are coalesced.
// ---------------------------------------------------------------------------
__global__ void gemm_part() {
    const int bx = blockIdx.x;
    const int kq = bx >> 4;              // k-split 0..15
    const int rt = (bx >> 2) & 3;        // row tile 0..3
    const int ct = bx & 3;               // col tile 0..3
    const int kb = kq * KT;
    const int r0 = rt * 64;
    const int c0 = ct * 64;
    const int tid = threadIdx.x;

    __shared__ float sA[KT][64];         // sA[k][row]  8 KB
    __shared__ float sB[KT][64];         // sB[k][col]  8 KB

#pragma unroll
    for (int j = 0; j < 2; j++) {
        const int idx = j * 256 + tid;   // 0..511
        const int row = idx >> 3;        // 0..63
        const int k4  = idx & 7;         // float4 along k-chunk
        const float4 va = *reinterpret_cast<const float4*>(
            g_A + (r0 + row) * DD + kb + k4 * 4);
        sA[k4 * 4 + 0][row] = va.x;
        sA[k4 * 4 + 1][row] = va.y;
        sA[k4 * 4 + 2][row] = va.z;
        sA[k4 * 4 + 3][row] = va.w;
        const float4 vb = *reinterpret_cast<const float4*>(
            g_F + (c0 + row) * DD + kb + k4 * 4);
        sB[k4 * 4 + 0][row] = vb.x;
        sB[k4 * 4 + 1][row] = vb.y;
        sB[k4 * 4 + 2][row] = vb.z;
        sB[k4 * 4 + 3][row] = vb.w;
    }
    __syncthreads();

    const int ty = tid >> 4;             // 0..15 -> rows r0 + ty*4 ..
    const int tx = tid & 15;             // 0..15 -> cols c0 + tx*4 ..

    float acc[4][4];
#pragma unroll
    for (int i = 0; i < 4; i++)
#pragma unroll
        for (int j = 0; j < 4; j++) acc[i][j] = 0.f;

#pragma unroll
    for (int k = 0; k < KT; k++) {
        const float4 a = *reinterpret_cast<const float4*>(&sA[k][ty * 4]);
        const float4 b = *reinterpret_cast<const float4*>(&sB[k][tx * 4]);
        acc[0][0] = fmaf(a.x, b.x, acc[0][0]);
        acc[0][1] = fmaf(a.x, b.y, acc[0][1]);
        acc[0][2] = fmaf(a.x, b.z, acc[0][2]);
        acc[0][3] = fmaf(a.x, b.w, acc[0][3]);
        acc[1][0] = fmaf(a.y, b.x, acc[1][0]);
        acc[1][1] = fmaf(a.y, b.y, acc[1][1]);
        acc[1][2] = fmaf(a.y, b.z, acc[1][2]);
        acc[1][3] = fmaf(a.y, b.w, acc[1][3]);
        acc[2][0] = fmaf(a.z, b.x, acc[2][0]);
        acc[2][1] = fmaf(a.z, b.y, acc[2][1]);
        acc[2][2] = fmaf(a.z, b.z, acc[2][2]);
        acc[2][3] = fmaf(a.z, b.w, acc[2][3]);
        acc[3][0] = fmaf(a.w, b.x, acc[3][0]);
        acc[3][1] = fmaf(a.w, b.y, acc[3][1]);
        acc[3][2] = fmaf(a.w, b.z, acc[3][2]);
        acc[3][3] = fmaf(a.w, b.w, acc[3][3]);
    }

    float* dst = g_part + ((size_t)kq * BB + (r0 + ty * 4)) * BB + (c0 + tx * 4);
#pragma unroll
    for (int i = 0; i < 4; i++)
        *reinterpret_cast<float4*>(dst + i * BB) =
            make_float4(acc[i][0], acc[i][1], acc[i][2], acc[i][3]);
}

// ---------------------------------------------------------------------------
// Kernel 3: one block per ROW (256 blocks x 256 threads; 12x the R13
// parallelism). Thread = column: 16 INDEPENDENT coalesced LDG.32 split
// partials, tree-summed (one exposed L2 latency), exp, 8-warp block
// reduction -> rowsum; diag captured; last-arriving block does final mean.
// ---------------------------------------------------------------------------
__global__ void lse_final(float* __restrict__ out) {
    const int row = blockIdx.x;
    const int c   = threadIdx.x;
    const int lane = c & 31;
    const int warp = c >> 5;

    // 16 independent loads (distinct regs), tree sum
    const float* p = g_part + row * BB + c;
    float t0  = p[ 0 * BB * BB], t1  = p[ 1 * BB * BB];
    float t2  = p[ 2 * BB * BB], t3  = p[ 3 * BB * BB];
    float t4  = p[ 4 * BB * BB], t5  = p[ 5 * BB * BB];
    float t6  = p[ 6 * BB * BB], t7  = p[ 7 * BB * BB];
    float t8  = p[ 8 * BB * BB], t9  = p[ 9 * BB * BB];
    float t10 = p[10 * BB * BB], t11 = p[11 * BB * BB];
    float t12 = p[12 * BB * BB], t13 = p[13 * BB * BB];
    float t14 = p[14 * BB * BB], t15 = p[15 * BB * BB];
    const float l = (((t0 + t1) + (t2 + t3)) + ((t4 + t5) + (t6 + t7)))
                  + (((t8 + t9) + (t10 + t11)) + ((t12 + t13) + (t14 + t15)));

    __shared__ float dv;
    if (c == row) dv = l;                // logits[row][row]

    // block-wide sum of exp(l) (no-max: logits are O(1), fp32-safe)
    float e = __expf(l);
#pragma unroll
    for (int o = 16; o; o >>= 1) e += __shfl_xor_sync(0xffffffffu, e, o);
    __shared__ float red[8];
    if (lane == 0) red[warp] = e;
    __syncthreads();

    if (c == 0) {
        float s = red[0];
#pragma unroll
        for (int i = 1; i < 8; i++) s += red[i];
        g_diag[row] = dv - logf(s);      // logp[row][row]
    }

    // ---- last-arriving block computes the final mean ----
    __shared__ unsigned int arrival;
    __syncthreads();
    if (c == 0) {
        __threadfence();
        arrival = atomicAdd(&g_cnt, 1u);
    }
    __syncthreads();

    if (arrival == (unsigned int)(BB - 1)) {
        __threadfence();
        volatile float* vd = g_diag;
        float v = vd[c];                 // 256 threads == 256 rows
#pragma unroll
        for (int o = 16; o; o >>= 1) v += __shfl_xor_sync(0xffffffffu, v, o);
        if (lane == 0) red[warp] = v;
        __syncthreads();
        if (c == 0) {
            float s = red[0];
#pragma unroll
            for (int i = 1; i < 8; i++) s += red[i];
            out[0] = -s * (1.0f / 256.0f);
        }
    }
}

extern "C" void kernel_launch(void* const* d_in, const int* in_sizes, int n_in,
                              void* d_out, int out_size) {
    const float* face = (const float*)d_in[0];  // (256, 32, 512)
    const float* ner  = (const float*)d_in[1];  // (256, 32, 512)
    float* out = (float*)d_out;

    reduce_spans<<<2 * BB, 512>>>(face, ner);
    gemm_part<<<256, 256>>>();
    lse_final<<<BB, 256>>>(out);
}

// round 17
// speedup vs baseline: 1.0152x; 1.0152x over previous
#include <cuda_runtime.h>
#include <math.h>

#define BB 256   // batch
#define NS 32    // spans
#define DD 512   // feature dim

#define KT 32    // k-chunk per gemm block (16 k-splits)
#define NSPLIT 16

// Scratch (allocation-free rule: __device__ globals)
__device__ float g_A[BB * DD];              // ner span-sums [b][d], pre-scaled 1/1024
__device__ float g_F[BB * DD];              // face span-sums [c][d]
__device__ float g_part[NSPLIT * BB * BB];  // per-k-split logits partials (4 MB)
__device__ float g_diag[BB];                // logp[b][b]
__device__ unsigned int g_cnt;              // lse arrival counter

// ---------------------------------------------------------------------------
// Kernel 1: span reductions. 1024 blocks x 256 threads: 2 blocks per row
// (64 d4-columns each), 4 span-groups of 8. 8 blocks/SM max -> single
// full wave (512x512 config had 3 blocks/SM -> 444+68 two-wave tail).
// Load structure identical to R14: 2 batches of 4 independent LDG.128.
// ---------------------------------------------------------------------------
__global__ void reduce_spans(
        const float* __restrict__ face, const float* __restrict__ ner) {
    const int blk = blockIdx.x;
    const int tid = threadIdx.x;
    const int half = blk & 1;            // which 64-column half of the row
    const int rid  = blk >> 1;           // 0..511
    const int t4   = (tid & 63) + half * 64;  // float4 column 0..127
    const int grp  = tid >> 6;           // span group 0..3 (8 spans each)

    if (blk == 0 && tid == 0) g_cnt = 0u;

    const bool is_ner = (rid < BB);
    const int row = is_ner ? rid : rid - BB;
    const float4* src = reinterpret_cast<const float4*>(
        (is_ner ? ner : face) + (size_t)row * NS * DD) + grp * 8 * (DD / 4) + t4;

    float4 s = make_float4(0.f, 0.f, 0.f, 0.f);
#pragma unroll
    for (int j = 0; j < 2; j++) {
        // 4 independent loads, tree-summed, then folded into s
        const float4 v0 = src[(j * 4 + 0) * (DD / 4)];
        const float4 v1 = src[(j * 4 + 1) * (DD / 4)];
        const float4 v2 = src[(j * 4 + 2) * (DD / 4)];
        const float4 v3 = src[(j * 4 + 3) * (DD / 4)];
        const float4 a01 = make_float4(v0.x + v1.x, v0.y + v1.y,
                                       v0.z + v1.z, v0.w + v1.w);
        const float4 a23 = make_float4(v2.x + v3.x, v2.y + v3.y,
                                       v2.z + v3.z, v2.w + v3.w);
        s.x += a01.x + a23.x;
        s.y += a01.y + a23.y;
        s.z += a01.z + a23.z;
        s.w += a01.w + a23.w;
    }

    __shared__ float4 sp[3][64];
    if (grp > 0) sp[grp - 1][tid & 63] = s;
    __syncthreads();

    if (grp == 0) {
#pragma unroll
        for (int i = 0; i < 3; i++) {
            float4 v = sp[i][tid & 63];
            s.x += v.x; s.y += v.y; s.z += v.z; s.w += v.w;
        }
        if (is_ner) {
            const float inv = 1.0f / 1024.0f;   // fold the 1/(N1*N2) mean
            s.x *= inv; s.y *= inv; s.z *= inv; s.w *= inv;
            reinterpret_cast<float4*>(g_A + row * DD)[t4] = s;
        } else {
            reinterpret_cast<float4*>(g_F + row * DD)[t4] = s;
        }
    }
}

// ---------------------------------------------------------------------------
// Kernel 2: smem-staged register-blocked SGEMM partial.
// Block = 64x64 C-tile, k-chunk of 32. Grid = 16 tiles x 16 k-splits = 256
// blocks x 256 threads. Mainloop per k: 2 x LDS.128 + 16 FMA (4x4 reg tile).
// Output: 4 plain STG.128 per thread into this k-split's private slice,
// layout g_part[ks][row][col] so kernel 3's reads are coalesced.
// ---------------------------------------------------------------------------
__global__ void gemm_part() {
    const int bx = blockIdx.x;
    const int kq = bx >> 4;              // k-split 0..15
    const int rt = (bx >> 2) & 3;        // row tile 0..3
    const int ct = bx & 3;               // col tile 0..3
    const int kb = kq * KT;
    const int r0 = rt * 64;
    const int c0 = ct * 64;
    const int tid = threadIdx.x;

    __shared__ float sA[KT][64];         // sA[k][row]  8 KB
    __shared__ float sB[KT][64];         // sB[k][col]  8 KB

#pragma unroll
    for (int j = 0; j < 2; j++) {
        const int idx = j * 256 + tid;   // 0..511
        const int row = idx >> 3;        // 0..63
        const int k4  = idx & 7;         // float4 along k-chunk
        const float4 va = *reinterpret_cast<const float4*>(
            g_A + (r0 + row) * DD + kb + k4 * 4);
        sA[k4 * 4 + 0][row] = va.x;
        sA[k4 * 4 + 1][row] = va.y;
        sA[k4 * 4 + 2][row] = va.z;
        sA[k4 * 4 + 3][row] = va.w;
        const float4 vb = *reinterpret_cast<const float4*>(
            g_F + (c0 + row) * DD + kb + k4 * 4);
        sB[k4 * 4 + 0][row] = vb.x;
        sB[k4 * 4 + 1][row] = vb.y;
        sB[k4 * 4 + 2][row] = vb.z;
        sB[k4 * 4 + 3][row] = vb.w;
    }
    __syncthreads();

    const int ty = tid >> 4;             // 0..15 -> rows r0 + ty*4 ..
    const int tx = tid & 15;             // 0..15 -> cols c0 + tx*4 ..

    float acc[4][4];
#pragma unroll
    for (int i = 0; i < 4; i++)
#pragma unroll
        for (int j = 0; j < 4; j++) acc[i][j] = 0.f;

#pragma unroll
    for (int k = 0; k < KT; k++) {
        const float4 a = *reinterpret_cast<const float4*>(&sA[k][ty * 4]);
        const float4 b = *reinterpret_cast<const float4*>(&sB[k][tx * 4]);
        acc[0][0] = fmaf(a.x, b.x, acc[0][0]);
        acc[0][1] = fmaf(a.x, b.y, acc[0][1]);
        acc[0][2] = fmaf(a.x, b.z, acc[0][2]);
        acc[0][3] = fmaf(a.x, b.w, acc[0][3]);
        acc[1][0] = fmaf(a.y, b.x, acc[1][0]);
        acc[1][1] = fmaf(a.y, b.y, acc[1][1]);
        acc[1][2] = fmaf(a.y, b.z, acc[1][2]);
        acc[1][3] = fmaf(a.y, b.w, acc[1][3]);
        acc[2][0] = fmaf(a.z, b.x, acc[2][0]);
        acc[2][1] = fmaf(a.z, b.y, acc[2][1]);
        acc[2][2] = fmaf(a.z, b.z, acc[2][2]);
        acc[2][3] = fmaf(a.z, b.w, acc[2][3]);
        acc[3][0] = fmaf(a.w, b.x, acc[3][0]);
        acc[3][1] = fmaf(a.w, b.y, acc[3][1]);
        acc[3][2] = fmaf(a.w, b.z, acc[3][2]);
        acc[3][3] = fmaf(a.w, b.w, acc[3][3]);
    }

    float* dst = g_part + ((size_t)kq * BB + (r0 + ty * 4)) * BB + (c0 + tx * 4);
#pragma unroll
    for (int i = 0; i < 4; i++)
        *reinterpret_cast<float4*>(dst + i * BB) =
            make_float4(acc[i][0], acc[i][1], acc[i][2], acc[i][3]);
}

// ---------------------------------------------------------------------------
// Kernel 3: one block per ROW (256 blocks x 256 threads).
// Thread = column: 16 INDEPENDENT coalesced LDG.32 split partials,
// tree-summed (one exposed L2 latency), exp, 8-warp block reduction ->
// rowsum; diag captured; last-arriving block does final mean.
// ---------------------------------------------------------------------------
__global__ void lse_final(float* __restrict__ out) {
    const int row = blockIdx.x;
    const int c   = threadIdx.x;
    const int lane = c & 31;
    const int warp = c >> 5;

    // 16 independent loads (distinct regs), tree sum
    const float* p = g_part + row * BB + c;
    float t0  = p[ 0 * BB * BB], t1  = p[ 1 * BB * BB];
    float t2  = p[ 2 * BB * BB], t3  = p[ 3 * BB * BB];
    float t4  = p[ 4 * BB * BB], t5  = p[ 5 * BB * BB];
    float t6  = p[ 6 * BB * BB], t7  = p[ 7 * BB * BB];
    float t8  = p[ 8 * BB * BB], t9  = p[ 9 * BB * BB];
    float t10 = p[10 * BB * BB], t11 = p[11 * BB * BB];
    float t12 = p[12 * BB * BB], t13 = p[13 * BB * BB];
    float t14 = p[14 * BB * BB], t15 = p[15 * BB * BB];
    const float l = (((t0 + t1) + (t2 + t3)) + ((t4 + t5) + (t6 + t7)))
                  + (((t8 + t9) + (t10 + t11)) + ((t12 + t13) + (t14 + t15)));

    __shared__ float dv;
    if (c == row) dv = l;                // logits[row][row]

    // block-wide sum of exp(l) (no-max: logits are O(1), fp32-safe)
    float e = __expf(l);
#pragma unroll
    for (int o = 16; o; o >>= 1) e += __shfl_xor_sync(0xffffffffu, e, o);
    __shared__ float red[8];
    if (lane == 0) red[warp] = e;
    __syncthreads();

    if (c == 0) {
        float s = red[0];
#pragma unroll
        for (int i = 1; i < 8; i++) s += red[i];
        g_diag[row] = dv - logf(s);      // logp[row][row]
    }

    // ---- last-arriving block computes the final mean ----
    __shared__ unsigned int arrival;
    __syncthreads();
    if (c == 0) {
        __threadfence();
        arrival = atomicAdd(&g_cnt, 1u);
    }
    __syncthreads();

    if (arrival == (unsigned int)(BB - 1)) {
        __threadfence();
        volatile float* vd = g_diag;
        float v = vd[c];                 // 256 threads == 256 rows
#pragma unroll
        for (int o = 16; o; o >>= 1) v += __shfl_xor_sync(0xffffffffu, v, o);
        if (lane == 0) red[warp] = v;
        __syncthreads();
        if (c == 0) {
            float s = red[0];
#pragma unroll
            for (int i = 1; i < 8; i++) s += red[i];
            out[0] = -s * (1.0f / 256.0f);
        }
    }
}

extern "C" void kernel_launch(void* const* d_in, const int* in_sizes, int n_in,
                              void* d_out, int out_size) {
    const float* face = (const float*)d_in[0];  // (256, 32, 512)
    const float* ner  = (const float*)d_in[1];  // (256, 32, 512)
    float* out = (float*)d_out;

    reduce_spans<<<2 * 2 * BB, 256>>>(face, ner);
    gemm_part<<<256, 256>>>();
    lse_final<<<BB, 256>>>(out);
}